// round 1
// baseline (speedup 1.0000x reference)
#include <cuda_runtime.h>
#include <cuda_bf16.h>
#include <mma.h>

using namespace nvcuda;

// ---------------- problem constants ----------------
#define L_SEQ   1024
#define D_MODEL 768
#define D_INNER 1536
#define D_STATE 64
#define D_CONV  4
#define DT_RANK 48
#define DBL_N   (DT_RANK + 2*D_STATE)   // 176
#define LN_EPS  1e-5f

// ---------------- scratch (no allocations allowed) ----------------
__device__ float g_xn [L_SEQ * D_MODEL];
__device__ float g_xz [L_SEQ * 2 * D_INNER];
__device__ float g_xc [L_SEQ * D_INNER];
__device__ float g_dbl[L_SEQ * DBL_N];
__device__ float g_dt [L_SEQ * D_INNER];
__device__ float g_xcT[D_INNER * L_SEQ];
__device__ float g_dtT[D_INNER * L_SEQ];
__device__ float g_y  [L_SEQ * D_INNER];

// ---------------- LayerNorm ----------------
__global__ void ln_kernel(const float* __restrict__ x, const float* __restrict__ g,
                          const float* __restrict__ b, float* __restrict__ xn)
{
    int t = blockIdx.x;
    const float* xr = x + t * D_MODEL;
    float s = 0.f, s2 = 0.f;
    for (int i = threadIdx.x; i < D_MODEL; i += 256) {
        float v = xr[i];
        s += v; s2 += v * v;
    }
    #pragma unroll
    for (int o = 16; o; o >>= 1) {
        s  += __shfl_xor_sync(0xffffffffu, s,  o);
        s2 += __shfl_xor_sync(0xffffffffu, s2, o);
    }
    __shared__ float ss[8], ss2[8];
    __shared__ float mu_s, rstd_s;
    if ((threadIdx.x & 31) == 0) { ss[threadIdx.x >> 5] = s; ss2[threadIdx.x >> 5] = s2; }
    __syncthreads();
    if (threadIdx.x == 0) {
        float a = 0.f, a2 = 0.f;
        #pragma unroll
        for (int i = 0; i < 8; i++) { a += ss[i]; a2 += ss2[i]; }
        float mu = a / (float)D_MODEL;
        float var = a2 / (float)D_MODEL - mu * mu;
        mu_s = mu;
        rstd_s = rsqrtf(var + LN_EPS);
    }
    __syncthreads();
    float mu = mu_s, rstd = rstd_s;
    for (int i = threadIdx.x; i < D_MODEL; i += 256)
        xn[t * D_MODEL + i] = (xr[i] - mu) * rstd * g[i] + b[i];
}

// ---------------- generic tf32 WMMA GEMM: C = A(MxK) * B(KxN) (+epilogue) ----------------
// epilogue: 0 = none, 1 = softplus(v + bias[col])
__global__ void gemm_tf32(const float* __restrict__ A, int lda,
                          const float* __restrict__ B, int ldb,
                          float* __restrict__ C, int ldc,
                          int M, int N, int K,
                          const float* __restrict__ bias, int epilogue)
{
    __shared__ float As[64][40];   // row-major MxK tile, ld=40 (mult of 8)
    __shared__ float Bs[32][72];   // row-major KxN tile, ld=72 (mult of 8)
    __shared__ float Cs[64][72];

    int tid = threadIdx.x;
    int warp = tid >> 5;
    int wr = warp >> 1, wc = warp & 1;
    int row_base = blockIdx.y * 64;
    int col_base = blockIdx.x * 64;

    wmma::fragment<wmma::accumulator, 16, 16, 8, float> acc[2][2];
    #pragma unroll
    for (int i = 0; i < 2; i++)
        #pragma unroll
        for (int j = 0; j < 2; j++)
            wmma::fill_fragment(acc[i][j], 0.f);

    for (int k0 = 0; k0 < K; k0 += 32) {
        #pragma unroll
        for (int e = tid; e < 64 * 32; e += 128) {
            int r = e >> 5, c = e & 31;
            int gr = row_base + r, gc = k0 + c;
            As[r][c] = (gr < M && gc < K) ? A[gr * lda + gc] : 0.f;
        }
        #pragma unroll
        for (int e = tid; e < 32 * 64; e += 128) {
            int r = e >> 6, c = e & 63;
            int gr = k0 + r, gc = col_base + c;
            Bs[r][c] = (gr < K && gc < N) ? B[gr * ldb + gc] : 0.f;
        }
        __syncthreads();

        #pragma unroll
        for (int kk = 0; kk < 32; kk += 8) {
            wmma::fragment<wmma::matrix_a, 16, 16, 8, wmma::precision::tf32, wmma::row_major> a[2];
            wmma::fragment<wmma::matrix_b, 16, 16, 8, wmma::precision::tf32, wmma::row_major> bf[2];
            wmma::load_matrix_sync(a[0], &As[wr * 32][kk], 40);
            wmma::load_matrix_sync(a[1], &As[wr * 32 + 16][kk], 40);
            wmma::load_matrix_sync(bf[0], &Bs[kk][wc * 32], 72);
            wmma::load_matrix_sync(bf[1], &Bs[kk][wc * 32 + 16], 72);
            #pragma unroll
            for (int i = 0; i < 2; i++) {
                #pragma unroll
                for (int e = 0; e < a[i].num_elements; e++)
                    a[i].x[e] = wmma::__float_to_tf32(a[i].x[e]);
                #pragma unroll
                for (int e = 0; e < bf[i].num_elements; e++)
                    bf[i].x[e] = wmma::__float_to_tf32(bf[i].x[e]);
            }
            #pragma unroll
            for (int i = 0; i < 2; i++)
                #pragma unroll
                for (int j = 0; j < 2; j++)
                    wmma::mma_sync(acc[i][j], a[i], bf[j], acc[i][j]);
        }
        __syncthreads();
    }

    #pragma unroll
    for (int i = 0; i < 2; i++)
        #pragma unroll
        for (int j = 0; j < 2; j++)
            wmma::store_matrix_sync(&Cs[wr * 32 + i * 16][wc * 32 + j * 16], acc[i][j], 72,
                                    wmma::mem_row_major);
    __syncthreads();

    #pragma unroll
    for (int e = tid; e < 64 * 64; e += 128) {
        int r = e >> 6, c = e & 63;
        int gr = row_base + r, gc = col_base + c;
        if (gr < M && gc < N) {
            float v = Cs[r][c];
            if (epilogue == 1) {
                v += bias[gc];
                v = fmaxf(v, 0.f) + log1pf(__expf(-fabsf(v)));   // stable softplus
            }
            C[gr * ldc + gc] = v;
        }
    }
}

// ---------------- depthwise causal conv (d_conv=4) + SiLU ----------------
__global__ void conv_silu_kernel(const float* __restrict__ xz,
                                 const float* __restrict__ conv_w,
                                 const float* __restrict__ conv_b,
                                 float* __restrict__ xc)
{
    int idx = blockIdx.x * 256 + threadIdx.x;
    if (idx >= L_SEQ * D_INNER) return;
    int t = idx / D_INNER, d = idx - t * D_INNER;
    float acc = conv_b[d];
    #pragma unroll
    for (int k = 0; k < D_CONV; k++) {
        int ti = t + k - (D_CONV - 1);
        if (ti >= 0) acc += xz[ti * (2 * D_INNER) + d] * conv_w[d * D_CONV + k];
    }
    float e = __expf(-acc);
    acc = acc * __frcp_rn(1.f + e);  // silu
    xc[t * D_INNER + d] = acc;
}

// ---------------- transpose [t][d] -> [d][t] for dt and xc ----------------
__global__ void transpose2_kernel(const float* __restrict__ in0, float* __restrict__ out0,
                                  const float* __restrict__ in1, float* __restrict__ out1)
{
    __shared__ float tile[32][33];
    const float* in  = blockIdx.z ? in1  : in0;
    float*       out = blockIdx.z ? out1 : out0;
    int t0 = blockIdx.y * 32;
    int d0 = blockIdx.x * 32;
    int tx = threadIdx.x, ty = threadIdx.y;
    #pragma unroll
    for (int i = 0; i < 32; i += 8)
        tile[ty + i][tx] = in[(t0 + ty + i) * D_INNER + d0 + tx];
    __syncthreads();
    #pragma unroll
    for (int i = 0; i < 32; i += 8)
        out[(d0 + ty + i) * L_SEQ + t0 + tx] = tile[tx][ty + i];
}

// ---------------- selective scan + skip + gating ----------------
// 1 warp = 1 channel d; lane l owns states l and l+32. 8 warps/CTA share B/C in smem.
__global__ void scan_kernel(const float* __restrict__ dbl,
                            const float* __restrict__ dtT,
                            const float* __restrict__ xcT,
                            const float* __restrict__ xz,
                            const float* __restrict__ A_log,
                            const float* __restrict__ D_skip,
                            float* __restrict__ y)
{
    __shared__ float bc[32][128];   // [step][ B(64) | C(64) ]
    int warp = threadIdx.x >> 5, lane = threadIdx.x & 31;
    int d = blockIdx.x * 8 + warp;

    float A0 = -__expf(A_log[d * D_STATE + lane]);
    float A1 = -__expf(A_log[d * D_STATE + lane + 32]);
    float Dd = D_skip[d];
    float h0 = 0.f, h1 = 0.f;

    for (int tc = 0; tc < L_SEQ; tc += 32) {
        float dt_r = dtT[d * L_SEQ + tc + lane];
        float xc_r = xcT[d * L_SEQ + tc + lane];
        __syncthreads();
        #pragma unroll
        for (int e = threadIdx.x; e < 32 * 128; e += 256) {
            int r = e >> 7, c = e & 127;
            bc[r][c] = dbl[(tc + r) * DBL_N + DT_RANK + c];
        }
        __syncthreads();
        #pragma unroll 4
        for (int j = 0; j < 32; j++) {
            float dt_t = __shfl_sync(0xffffffffu, dt_r, j);
            float x_t  = __shfl_sync(0xffffffffu, xc_r, j);
            float b0 = bc[j][lane],      b1 = bc[j][lane + 32];
            float c0 = bc[j][64 + lane], c1 = bc[j][96 + lane];
            float dx = dt_t * x_t;
            h0 = __expf(dt_t * A0) * h0 + dx * b0;
            h1 = __expf(dt_t * A1) * h1 + dx * b1;
            float ys = h0 * c0 + h1 * c1;
            ys += __shfl_xor_sync(0xffffffffu, ys, 16);
            ys += __shfl_xor_sync(0xffffffffu, ys, 8);
            ys += __shfl_xor_sync(0xffffffffu, ys, 4);
            ys += __shfl_xor_sync(0xffffffffu, ys, 2);
            ys += __shfl_xor_sync(0xffffffffu, ys, 1);
            if (lane == 0) {
                int t = tc + j;
                float zv = xz[t * (2 * D_INNER) + D_INNER + d];
                float sz = zv * __frcp_rn(1.f + __expf(-zv));     // silu(z)
                y[t * D_INNER + d] = (ys + x_t * Dd) * sz;
            }
        }
    }
}

// ---------------- host launcher ----------------
extern "C" void kernel_launch(void* const* d_in, const int* in_sizes, int n_in,
                              void* d_out, int out_size)
{
    const float* x      = (const float*)d_in[0];
    const float* ln_g   = (const float*)d_in[1];
    const float* ln_b   = (const float*)d_in[2];
    const float* W_in   = (const float*)d_in[3];
    const float* conv_w = (const float*)d_in[4];
    const float* conv_b = (const float*)d_in[5];
    const float* W_x    = (const float*)d_in[6];
    const float* W_dt   = (const float*)d_in[7];
    const float* b_dt   = (const float*)d_in[8];
    const float* A_log  = (const float*)d_in[9];
    const float* D_skip = (const float*)d_in[10];
    const float* W_out  = (const float*)d_in[11];
    float* out = (float*)d_out;

    float *xn, *xz, *xc, *dbl, *dt, *xcT, *dtT, *y;
    cudaGetSymbolAddress((void**)&xn,  g_xn);
    cudaGetSymbolAddress((void**)&xz,  g_xz);
    cudaGetSymbolAddress((void**)&xc,  g_xc);
    cudaGetSymbolAddress((void**)&dbl, g_dbl);
    cudaGetSymbolAddress((void**)&dt,  g_dt);
    cudaGetSymbolAddress((void**)&xcT, g_xcT);
    cudaGetSymbolAddress((void**)&dtT, g_dtT);
    cudaGetSymbolAddress((void**)&y,   g_y);

    // 1. LayerNorm
    ln_kernel<<<L_SEQ, 256>>>(x, ln_g, ln_b, xn);

    // 2. in-projection: xz = xn @ W_in   (1024 x 768 x 3072)
    gemm_tf32<<<dim3(2 * D_INNER / 64, L_SEQ / 64), 128>>>(
        xn, D_MODEL, W_in, 2 * D_INNER, xz, 2 * D_INNER,
        L_SEQ, 2 * D_INNER, D_MODEL, nullptr, 0);

    // 3. causal depthwise conv + SiLU
    conv_silu_kernel<<<(L_SEQ * D_INNER + 255) / 256, 256>>>(xz, conv_w, conv_b, xc);

    // 4. x-projection: dbl = xc @ W_x   (1024 x 1536 x 176)
    gemm_tf32<<<dim3((DBL_N + 63) / 64, L_SEQ / 64), 128>>>(
        xc, D_INNER, W_x, DBL_N, dbl, DBL_N,
        L_SEQ, DBL_N, D_INNER, nullptr, 0);

    // 5. dt = softplus(dt_raw @ W_dt + b_dt)   (1024 x 48 x 1536)
    gemm_tf32<<<dim3(D_INNER / 64, L_SEQ / 64), 128>>>(
        dbl, DBL_N, W_dt, D_INNER, dt, D_INNER,
        L_SEQ, D_INNER, DT_RANK, b_dt, 1);

    // 6. transpose dt, xc to [d][t]
    transpose2_kernel<<<dim3(D_INNER / 32, L_SEQ / 32, 2), dim3(32, 8)>>>(dt, dtT, xc, xcT);

    // 7. selective scan + D-skip + z gating
    scan_kernel<<<D_INNER / 8, 256>>>(dbl, dtT, xcT, xz, A_log, D_skip, y);

    // 8. out-projection: out = y @ W_out   (1024 x 1536 x 768)
    gemm_tf32<<<dim3(D_MODEL / 64, L_SEQ / 64), 128>>>(
        y, D_INNER, W_out, D_MODEL, out, D_MODEL,
        L_SEQ, D_MODEL, D_INNER, nullptr, 0);
}

// round 3
// speedup vs baseline: 1.6861x; 1.6861x over previous
#include <cstdint>
#include <cuda_runtime.h>
#include <cuda_bf16.h>
#include <mma.h>

using namespace nvcuda;

// ---------------- problem constants ----------------
#define L_SEQ   1024
#define D_MODEL 768
#define D_INNER 1536
#define D_STATE 64
#define D_CONV  4
#define DT_RANK 48
#define DBL_N   (DT_RANK + 2*D_STATE)   // 176
#define LN_EPS  1e-5f

// GEMM tiling
#define BM 128
#define BN 64
#define BK 32
#define ALD 36     // As leading dim (floats), 144B rows (16B-aligned, bank-rotating)
#define BLD 68     // Bs leading dim, 272B rows
#define CLD 68
#define GEMM_THREADS 256
#define GEMM_SMEM ((BM*ALD + BK*BLD) * 2 * 4)   // double-buffered stages, bytes

// ---------------- scratch (no allocations allowed) ----------------
__device__ float g_xn [L_SEQ * D_MODEL];
__device__ float g_xz [L_SEQ * 2 * D_INNER];
__device__ float g_xc [L_SEQ * D_INNER];
__device__ float g_dbl[L_SEQ * DBL_N];
__device__ float g_dt [L_SEQ * D_INNER];
__device__ float g_xcT[D_INNER * L_SEQ];
__device__ float g_dtT[D_INNER * L_SEQ];
__device__ float g_y  [L_SEQ * D_INNER];

// ---------------- cp.async helpers ----------------
__device__ __forceinline__ void cp_async16(void* smem_dst, const void* gmem_src) {
    unsigned int dst = (unsigned int)__cvta_generic_to_shared(smem_dst);
    asm volatile("cp.async.cg.shared.global [%0], [%1], 16;\n" :: "r"(dst), "l"(gmem_src));
}
__device__ __forceinline__ void cp_async_commit() {
    asm volatile("cp.async.commit_group;\n");
}
template<int N>
__device__ __forceinline__ void cp_async_wait() {
    asm volatile("cp.async.wait_group %0;\n" :: "n"(N));
}

// ---------------- LayerNorm ----------------
__global__ void ln_kernel(const float* __restrict__ x, const float* __restrict__ g,
                          const float* __restrict__ b, float* __restrict__ xn)
{
    int t = blockIdx.x;
    const float* xr = x + t * D_MODEL;
    float s = 0.f, s2 = 0.f;
    for (int i = threadIdx.x; i < D_MODEL; i += 256) {
        float v = xr[i];
        s += v; s2 += v * v;
    }
    #pragma unroll
    for (int o = 16; o; o >>= 1) {
        s  += __shfl_xor_sync(0xffffffffu, s,  o);
        s2 += __shfl_xor_sync(0xffffffffu, s2, o);
    }
    __shared__ float ss[8], ss2[8];
    __shared__ float mu_s, rstd_s;
    if ((threadIdx.x & 31) == 0) { ss[threadIdx.x >> 5] = s; ss2[threadIdx.x >> 5] = s2; }
    __syncthreads();
    if (threadIdx.x == 0) {
        float a = 0.f, a2 = 0.f;
        #pragma unroll
        for (int i = 0; i < 8; i++) { a += ss[i]; a2 += ss2[i]; }
        float mu = a / (float)D_MODEL;
        float var = a2 / (float)D_MODEL - mu * mu;
        mu_s = mu;
        rstd_s = rsqrtf(var + LN_EPS);
    }
    __syncthreads();
    float mu = mu_s, rstd = rstd_s;
    for (int i = threadIdx.x; i < D_MODEL; i += 256)
        xn[t * D_MODEL + i] = (xr[i] - mu) * rstd * g[i] + b[i];
}

// ---------------- tf32 WMMA GEMM, cp.async double-buffered ----------------
// C[M,N] = A[M,K] * B[K,N]; epilogue: 0 = none, 1 = softplus(v + bias[col])
// Requires M % 128 == 0 and N, K % 4 == 0 (true for all 4 GEMMs here).
__global__ void __launch_bounds__(GEMM_THREADS)
gemm_tf32(const float* __restrict__ A, int lda,
          const float* __restrict__ B, int ldb,
          float* __restrict__ C, int ldc,
          int M, int N, int K,
          const float* __restrict__ bias, int epilogue)
{
    extern __shared__ float smem[];
    float* As[2] = { smem, smem + BM*ALD + BK*BLD };
    float* Bs[2] = { smem + BM*ALD, smem + 2*BM*ALD + BK*BLD };

    const int tid  = threadIdx.x;
    const int warp = tid >> 5;
    const int wr   = warp >> 1;      // 0..3
    const int wc   = warp & 1;       // 0..1
    const int row_base = blockIdx.y * BM;
    const int col_base = blockIdx.x * BN;

    const float4 zero4 = make_float4(0.f, 0.f, 0.f, 0.f);

    // stage loader: fill As[s]/Bs[s] with K-tile starting at k0
    auto load_stage = [&](int s, int k0) {
        // A tile: 128 rows x 32 cols = 1024 float4 chunks, 4 per thread
        #pragma unroll
        for (int i = 0; i < 4; i++) {
            int idx = tid + i * GEMM_THREADS;
            int r = idx >> 3, ch = idx & 7;
            int gc = k0 + ch * 4;
            float* dst = &As[s][r * ALD + ch * 4];
            if (gc + 4 <= K) cp_async16(dst, &A[(row_base + r) * lda + gc]);
            else             *(float4*)dst = zero4;
        }
        // B tile: 32 rows x 64 cols = 512 float4 chunks, 2 per thread
        #pragma unroll
        for (int i = 0; i < 2; i++) {
            int idx = tid + i * GEMM_THREADS;
            int r = idx >> 4, ch = idx & 15;
            int gr = k0 + r, gc = col_base + ch * 4;
            float* dst = &Bs[s][r * BLD + ch * 4];
            if (gr < K && gc + 4 <= N) cp_async16(dst, &B[gr * ldb + gc]);
            else                       *(float4*)dst = zero4;
        }
        cp_async_commit();
    };

    wmma::fragment<wmma::accumulator, 16, 16, 8, float> acc[2][2];
    #pragma unroll
    for (int i = 0; i < 2; i++)
        #pragma unroll
        for (int j = 0; j < 2; j++)
            wmma::fill_fragment(acc[i][j], 0.f);

    const int ntiles = (K + BK - 1) / BK;
    load_stage(0, 0);

    for (int kt = 0; kt < ntiles; kt++) {
        int s = kt & 1;
        if (kt + 1 < ntiles) {
            load_stage(s ^ 1, (kt + 1) * BK);
            cp_async_wait<1>();
        } else {
            cp_async_wait<0>();
        }
        __syncthreads();

        const float* Ac = As[s];
        const float* Bc = Bs[s];
        #pragma unroll
        for (int kk = 0; kk < BK; kk += 8) {
            wmma::fragment<wmma::matrix_a, 16, 16, 8, wmma::precision::tf32, wmma::row_major> af[2];
            wmma::fragment<wmma::matrix_b, 16, 16, 8, wmma::precision::tf32, wmma::row_major> bf[2];
            wmma::load_matrix_sync(af[0], &Ac[(wr * 32)      * ALD + kk], ALD);
            wmma::load_matrix_sync(af[1], &Ac[(wr * 32 + 16) * ALD + kk], ALD);
            wmma::load_matrix_sync(bf[0], &Bc[kk * BLD + wc * 32],      BLD);
            wmma::load_matrix_sync(bf[1], &Bc[kk * BLD + wc * 32 + 16], BLD);
            #pragma unroll
            for (int i = 0; i < 2; i++) {
                #pragma unroll
                for (int e = 0; e < af[i].num_elements; e++)
                    af[i].x[e] = wmma::__float_to_tf32(af[i].x[e]);
                #pragma unroll
                for (int e = 0; e < bf[i].num_elements; e++)
                    bf[i].x[e] = wmma::__float_to_tf32(bf[i].x[e]);
            }
            #pragma unroll
            for (int i = 0; i < 2; i++)
                #pragma unroll
                for (int j = 0; j < 2; j++)
                    wmma::mma_sync(acc[i][j], af[i], bf[j], acc[i][j]);
        }
        __syncthreads();
    }

    // epilogue through smem (reuse stage memory)
    float* Cs = smem;
    #pragma unroll
    for (int i = 0; i < 2; i++)
        #pragma unroll
        for (int j = 0; j < 2; j++)
            wmma::store_matrix_sync(&Cs[(wr * 32 + i * 16) * CLD + wc * 32 + j * 16],
                                    acc[i][j], CLD, wmma::mem_row_major);
    __syncthreads();

    #pragma unroll
    for (int e = tid; e < BM * BN; e += GEMM_THREADS) {
        int r = e >> 6, c = e & 63;
        int gr = row_base + r, gc = col_base + c;
        if (gr < M && gc < N) {
            float v = Cs[r * CLD + c];
            if (epilogue == 1) {
                v += bias[gc];
                v = fmaxf(v, 0.f) + log1pf(__expf(-fabsf(v)));   // stable softplus
            }
            C[gr * ldc + gc] = v;
        }
    }
}

// ---------------- depthwise causal conv (d_conv=4) + SiLU ----------------
__global__ void conv_silu_kernel(const float* __restrict__ xz,
                                 const float* __restrict__ conv_w,
                                 const float* __restrict__ conv_b,
                                 float* __restrict__ xc)
{
    int idx = blockIdx.x * 256 + threadIdx.x;
    if (idx >= L_SEQ * D_INNER) return;
    int t = idx / D_INNER, d = idx - t * D_INNER;
    float acc = conv_b[d];
    #pragma unroll
    for (int k = 0; k < D_CONV; k++) {
        int ti = t + k - (D_CONV - 1);
        if (ti >= 0) acc += xz[ti * (2 * D_INNER) + d] * conv_w[d * D_CONV + k];
    }
    float e = __expf(-acc);
    acc = acc * __frcp_rn(1.f + e);  // silu
    xc[t * D_INNER + d] = acc;
}

// ---------------- transpose [t][d] -> [d][t] for dt and xc ----------------
__global__ void transpose2_kernel(const float* __restrict__ in0, float* __restrict__ out0,
                                  const float* __restrict__ in1, float* __restrict__ out1)
{
    __shared__ float tile[32][33];
    const float* in  = blockIdx.z ? in1  : in0;
    float*       out = blockIdx.z ? out1 : out0;
    int t0 = blockIdx.y * 32;
    int d0 = blockIdx.x * 32;
    int tx = threadIdx.x, ty = threadIdx.y;
    #pragma unroll
    for (int i = 0; i < 32; i += 8)
        tile[ty + i][tx] = in[(t0 + ty + i) * D_INNER + d0 + tx];
    __syncthreads();
    #pragma unroll
    for (int i = 0; i < 32; i += 8)
        out[(d0 + ty + i) * L_SEQ + t0 + tx] = tile[tx][ty + i];
}

// ---------------- selective scan + skip + gating ----------------
// 1 warp = 1 channel d; lane l owns states l and l+32. 8 warps/CTA share B/C in smem.
__global__ void scan_kernel(const float* __restrict__ dbl,
                            const float* __restrict__ dtT,
                            const float* __restrict__ xcT,
                            const float* __restrict__ xz,
                            const float* __restrict__ A_log,
                            const float* __restrict__ D_skip,
                            float* __restrict__ y)
{
    __shared__ float bc[32][128];   // [step][ B(64) | C(64) ]
    int warp = threadIdx.x >> 5, lane = threadIdx.x & 31;
    int d = blockIdx.x * 8 + warp;

    float A0 = -__expf(A_log[d * D_STATE + lane]);
    float A1 = -__expf(A_log[d * D_STATE + lane + 32]);
    float Dd = D_skip[d];
    float h0 = 0.f, h1 = 0.f;

    for (int tc = 0; tc < L_SEQ; tc += 32) {
        float dt_r = dtT[d * L_SEQ + tc + lane];
        float xc_r = xcT[d * L_SEQ + tc + lane];
        __syncthreads();
        #pragma unroll
        for (int e = threadIdx.x; e < 32 * 128; e += 256) {
            int r = e >> 7, c = e & 127;
            bc[r][c] = dbl[(tc + r) * DBL_N + DT_RANK + c];
        }
        __syncthreads();
        #pragma unroll 4
        for (int j = 0; j < 32; j++) {
            float dt_t = __shfl_sync(0xffffffffu, dt_r, j);
            float x_t  = __shfl_sync(0xffffffffu, xc_r, j);
            float b0 = bc[j][lane],      b1 = bc[j][lane + 32];
            float c0 = bc[j][64 + lane], c1 = bc[j][96 + lane];
            float dx = dt_t * x_t;
            h0 = __expf(dt_t * A0) * h0 + dx * b0;
            h1 = __expf(dt_t * A1) * h1 + dx * b1;
            float ys = h0 * c0 + h1 * c1;
            ys += __shfl_xor_sync(0xffffffffu, ys, 16);
            ys += __shfl_xor_sync(0xffffffffu, ys, 8);
            ys += __shfl_xor_sync(0xffffffffu, ys, 4);
            ys += __shfl_xor_sync(0xffffffffu, ys, 2);
            ys += __shfl_xor_sync(0xffffffffu, ys, 1);
            if (lane == 0) {
                int t = tc + j;
                float zv = xz[t * (2 * D_INNER) + D_INNER + d];
                float sz = zv * __frcp_rn(1.f + __expf(-zv));     // silu(z)
                y[t * D_INNER + d] = (ys + x_t * Dd) * sz;
            }
        }
    }
}

// ---------------- host launcher ----------------
extern "C" void kernel_launch(void* const* d_in, const int* in_sizes, int n_in,
                              void* d_out, int out_size)
{
    const float* x      = (const float*)d_in[0];
    const float* ln_g   = (const float*)d_in[1];
    const float* ln_b   = (const float*)d_in[2];
    const float* W_in   = (const float*)d_in[3];
    const float* conv_w = (const float*)d_in[4];
    const float* conv_b = (const float*)d_in[5];
    const float* W_x    = (const float*)d_in[6];
    const float* W_dt   = (const float*)d_in[7];
    const float* b_dt   = (const float*)d_in[8];
    const float* A_log  = (const float*)d_in[9];
    const float* D_skip = (const float*)d_in[10];
    const float* W_out  = (const float*)d_in[11];
    float* out = (float*)d_out;

    float *xn, *xz, *xc, *dbl, *dt, *xcT, *dtT, *y;
    cudaGetSymbolAddress((void**)&xn,  g_xn);
    cudaGetSymbolAddress((void**)&xz,  g_xz);
    cudaGetSymbolAddress((void**)&xc,  g_xc);
    cudaGetSymbolAddress((void**)&dbl, g_dbl);
    cudaGetSymbolAddress((void**)&dt,  g_dt);
    cudaGetSymbolAddress((void**)&xcT, g_xcT);
    cudaGetSymbolAddress((void**)&dtT, g_dtT);
    cudaGetSymbolAddress((void**)&y,   g_y);

    static bool attr_done = false;
    if (!attr_done) {
        cudaFuncSetAttribute(gemm_tf32, cudaFuncAttributeMaxDynamicSharedMemorySize, GEMM_SMEM);
        attr_done = true;
    }

    // 1. LayerNorm
    ln_kernel<<<L_SEQ, 256>>>(x, ln_g, ln_b, xn);

    // 2. in-projection: xz = xn @ W_in   (1024 x 3072 x 768)
    gemm_tf32<<<dim3(2 * D_INNER / BN, L_SEQ / BM), GEMM_THREADS, GEMM_SMEM>>>(
        xn, D_MODEL, W_in, 2 * D_INNER, xz, 2 * D_INNER,
        L_SEQ, 2 * D_INNER, D_MODEL, nullptr, 0);

    // 3. causal depthwise conv + SiLU
    conv_silu_kernel<<<(L_SEQ * D_INNER + 255) / 256, 256>>>(xz, conv_w, conv_b, xc);

    // 4. x-projection: dbl = xc @ W_x   (1024 x 176 x 1536)
    gemm_tf32<<<dim3((DBL_N + BN - 1) / BN, L_SEQ / BM), GEMM_THREADS, GEMM_SMEM>>>(
        xc, D_INNER, W_x, DBL_N, dbl, DBL_N,
        L_SEQ, DBL_N, D_INNER, nullptr, 0);

    // 5. dt = softplus(dt_raw @ W_dt + b_dt)   (1024 x 1536 x 48)
    gemm_tf32<<<dim3(D_INNER / BN, L_SEQ / BM), GEMM_THREADS, GEMM_SMEM>>>(
        dbl, DBL_N, W_dt, D_INNER, dt, D_INNER,
        L_SEQ, D_INNER, DT_RANK, b_dt, 1);

    // 6. transpose dt, xc to [d][t]
    transpose2_kernel<<<dim3(D_INNER / 32, L_SEQ / 32, 2), dim3(32, 8)>>>(dt, dtT, xc, xcT);

    // 7. selective scan + D-skip + z gating
    scan_kernel<<<D_INNER / 8, 256>>>(dbl, dtT, xcT, xz, A_log, D_skip, y);

    // 8. out-projection: out = y @ W_out   (1024 x 768 x 1536)
    gemm_tf32<<<dim3(D_MODEL / BN, L_SEQ / BM), GEMM_THREADS, GEMM_SMEM>>>(
        y, D_INNER, W_out, D_MODEL, out, D_MODEL,
        L_SEQ, D_MODEL, D_INNER, nullptr, 0);
}

// round 4
// speedup vs baseline: 1.7638x; 1.0461x over previous
#include <cstdint>
#include <cuda_runtime.h>
#include <cuda_bf16.h>
#include <mma.h>

using namespace nvcuda;

// ---------------- problem constants ----------------
#define L_SEQ   1024
#define D_MODEL 768
#define D_INNER 1536
#define D_STATE 64
#define D_CONV  4
#define DT_RANK 48
#define DBL_N   (DT_RANK + 2*D_STATE)   // 176
#define LN_EPS  1e-5f

#define GEMM_THREADS 256

// ---------------- scratch (no allocations allowed) ----------------
__device__ float g_xn [L_SEQ * D_MODEL];
__device__ float g_xz [L_SEQ * 2 * D_INNER];
__device__ float g_xc [L_SEQ * D_INNER];
__device__ float g_dbl[L_SEQ * DBL_N];
__device__ float g_dt [L_SEQ * D_INNER];
__device__ float g_xcT[D_INNER * L_SEQ];
__device__ float g_dtT[D_INNER * L_SEQ];
__device__ float g_y  [L_SEQ * D_INNER];
__device__ float g_part[4 * L_SEQ * D_MODEL];   // split-K partials (max 3.2M floats)

// ---------------- cp.async helpers ----------------
__device__ __forceinline__ void cp_async16(void* smem_dst, const void* gmem_src) {
    unsigned int dst = (unsigned int)__cvta_generic_to_shared(smem_dst);
    asm volatile("cp.async.cg.shared.global [%0], [%1], 16;\n" :: "r"(dst), "l"(gmem_src));
}
__device__ __forceinline__ void cp_async_commit() {
    asm volatile("cp.async.commit_group;\n");
}
template<int N>
__device__ __forceinline__ void cp_async_wait() {
    asm volatile("cp.async.wait_group %0;\n" :: "n"(N));
}

// ---------------- LayerNorm ----------------
__global__ void ln_kernel(const float* __restrict__ x, const float* __restrict__ g,
                          const float* __restrict__ b, float* __restrict__ xn)
{
    int t = blockIdx.x;
    const float* xr = x + t * D_MODEL;
    float s = 0.f, s2 = 0.f;
    for (int i = threadIdx.x; i < D_MODEL; i += 256) {
        float v = xr[i];
        s += v; s2 += v * v;
    }
    #pragma unroll
    for (int o = 16; o; o >>= 1) {
        s  += __shfl_xor_sync(0xffffffffu, s,  o);
        s2 += __shfl_xor_sync(0xffffffffu, s2, o);
    }
    __shared__ float ss[8], ss2[8];
    __shared__ float mu_s, rstd_s;
    if ((threadIdx.x & 31) == 0) { ss[threadIdx.x >> 5] = s; ss2[threadIdx.x >> 5] = s2; }
    __syncthreads();
    if (threadIdx.x == 0) {
        float a = 0.f, a2 = 0.f;
        #pragma unroll
        for (int i = 0; i < 8; i++) { a += ss[i]; a2 += ss2[i]; }
        float mu = a / (float)D_MODEL;
        float var = a2 / (float)D_MODEL - mu * mu;
        mu_s = mu;
        rstd_s = rsqrtf(var + LN_EPS);
    }
    __syncthreads();
    float mu = mu_s, rstd = rstd_s;
    for (int i = threadIdx.x; i < D_MODEL; i += 256)
        xn[t * D_MODEL + i] = (xr[i] - mu) * rstd * g[i] + b[i];
}

// ---------------- templated tf32 WMMA GEMM, cp.async double-buffered, split-K ----------------
// Warp layout: 4 x 2 warps; warp tile = (BM/4) x (BN/2).
// If gridDim.z > 1: block z computes partial over K-slice [z*Kslice, min(K,(z+1)*Kslice)),
// written to C + z*M*ldc; epilogue is skipped for partials.
// epilogue: 0 = none, 1 = softplus(v + bias[col])
template<int BM, int BN, int BK>
__global__ void __launch_bounds__(GEMM_THREADS)
gemm_tf32(const float* __restrict__ A, int lda,
          const float* __restrict__ B, int ldb,
          float* __restrict__ C, int ldc,
          int M, int N, int K, int Kslice,
          const float* __restrict__ bias, int epilogue)
{
    constexpr int ALD = BK + 4;
    constexpr int BLD = BN + 4;
    constexpr int CLD = BN + 4;
    constexpr int FM = BM / 4 / 16;   // a-frags per warp (rows)
    constexpr int FN = BN / 2 / 16;   // b-frags per warp (cols)

    extern __shared__ float smem[];
    float* As[2] = { smem, smem + BM*ALD + BK*BLD };
    float* Bs[2] = { smem + BM*ALD, smem + 2*BM*ALD + BK*BLD };

    const int tid  = threadIdx.x;
    const int warp = tid >> 5;
    const int wr   = warp >> 1;      // 0..3
    const int wc   = warp & 1;       // 0..1
    const int row_base = blockIdx.y * BM;
    const int col_base = blockIdx.x * BN;

    const int k_begin = blockIdx.z * Kslice;
    const int k_end   = min(K, k_begin + Kslice);
    if (gridDim.z > 1) C += (size_t)blockIdx.z * M * ldc;

    const float4 zero4 = make_float4(0.f, 0.f, 0.f, 0.f);

    auto load_stage = [&](int s, int k0) {
        // A tile: BM x BK -> BM*BK/4 float4 chunks
        #pragma unroll
        for (int i = 0; i < BM*BK/4/GEMM_THREADS; i++) {
            int idx = tid + i * GEMM_THREADS;
            int r = idx / (BK/4), ch = idx % (BK/4);
            int gc = k0 + ch * 4;
            float* dst = &As[s][r * ALD + ch * 4];
            if (gc + 4 <= k_end) cp_async16(dst, &A[(row_base + r) * (size_t)lda + gc]);
            else                 *(float4*)dst = zero4;
        }
        // B tile: BK x BN -> BK*BN/4 chunks
        #pragma unroll
        for (int i = 0; i < BK*BN/4/GEMM_THREADS; i++) {
            int idx = tid + i * GEMM_THREADS;
            int r = idx / (BN/4), ch = idx % (BN/4);
            int gr = k0 + r, gc = col_base + ch * 4;
            float* dst = &Bs[s][r * BLD + ch * 4];
            if (gr < k_end && gc + 4 <= N) cp_async16(dst, &B[gr * (size_t)ldb + gc]);
            else                           *(float4*)dst = zero4;
        }
        cp_async_commit();
    };

    wmma::fragment<wmma::accumulator, 16, 16, 8, float> acc[FM][FN];
    #pragma unroll
    for (int i = 0; i < FM; i++)
        #pragma unroll
        for (int j = 0; j < FN; j++)
            wmma::fill_fragment(acc[i][j], 0.f);

    const int ntiles = (k_end - k_begin + BK - 1) / BK;
    load_stage(0, k_begin);

    for (int kt = 0; kt < ntiles; kt++) {
        int s = kt & 1;
        if (kt + 1 < ntiles) {
            load_stage(s ^ 1, k_begin + (kt + 1) * BK);
            cp_async_wait<1>();
        } else {
            cp_async_wait<0>();
        }
        __syncthreads();

        const float* Ac = As[s];
        const float* Bc = Bs[s];
        #pragma unroll
        for (int kk = 0; kk < BK; kk += 8) {
            wmma::fragment<wmma::matrix_a, 16, 16, 8, wmma::precision::tf32, wmma::row_major> af[FM];
            wmma::fragment<wmma::matrix_b, 16, 16, 8, wmma::precision::tf32, wmma::row_major> bf[FN];
            #pragma unroll
            for (int i = 0; i < FM; i++) {
                wmma::load_matrix_sync(af[i], &Ac[(wr * (BM/4) + i * 16) * ALD + kk], ALD);
                #pragma unroll
                for (int e = 0; e < af[i].num_elements; e++)
                    af[i].x[e] = wmma::__float_to_tf32(af[i].x[e]);
            }
            #pragma unroll
            for (int j = 0; j < FN; j++) {
                wmma::load_matrix_sync(bf[j], &Bc[kk * BLD + wc * (BN/2) + j * 16], BLD);
                #pragma unroll
                for (int e = 0; e < bf[j].num_elements; e++)
                    bf[j].x[e] = wmma::__float_to_tf32(bf[j].x[e]);
            }
            #pragma unroll
            for (int i = 0; i < FM; i++)
                #pragma unroll
                for (int j = 0; j < FN; j++)
                    wmma::mma_sync(acc[i][j], af[i], bf[j], acc[i][j]);
        }
        __syncthreads();
    }

    // epilogue through smem (reuse stage memory)
    float* Cs = smem;
    #pragma unroll
    for (int i = 0; i < FM; i++)
        #pragma unroll
        for (int j = 0; j < FN; j++)
            wmma::store_matrix_sync(&Cs[(wr * (BM/4) + i * 16) * CLD + wc * (BN/2) + j * 16],
                                    acc[i][j], CLD, wmma::mem_row_major);
    __syncthreads();

    #pragma unroll
    for (int e = tid; e < BM * BN; e += GEMM_THREADS) {
        int r = e / BN, c = e % BN;
        int gr = row_base + r, gc = col_base + c;
        if (gr < M && gc < N) {
            float v = Cs[r * CLD + c];
            if (epilogue == 1) {
                v += bias[gc];
                v = fmaxf(v, 0.f) + log1pf(__expf(-fabsf(v)));   // stable softplus
            }
            C[gr * (size_t)ldc + gc] = v;
        }
    }
}

// ---------------- split-K reduce: out[i] = sum_z part[z*stride + i] ----------------
__global__ void reduce_split(const float* __restrict__ part, float* __restrict__ out,
                             int n4, int nsplit, int stride)
{
    int i = blockIdx.x * 256 + threadIdx.x;
    if (i >= n4) return;
    const float4* p = (const float4*)part;
    int s4 = stride >> 2;
    float4 a = p[i];
    for (int z = 1; z < nsplit; z++) {
        float4 b = p[z * (size_t)s4 + i];
        a.x += b.x; a.y += b.y; a.z += b.z; a.w += b.w;
    }
    ((float4*)out)[i] = a;
}

// ---------------- depthwise causal conv (d_conv=4) + SiLU ----------------
__global__ void conv_silu_kernel(const float* __restrict__ xz,
                                 const float* __restrict__ conv_w,
                                 const float* __restrict__ conv_b,
                                 float* __restrict__ xc)
{
    int idx = blockIdx.x * 256 + threadIdx.x;
    if (idx >= L_SEQ * D_INNER) return;
    int t = idx / D_INNER, d = idx - t * D_INNER;
    float acc = conv_b[d];
    #pragma unroll
    for (int k = 0; k < D_CONV; k++) {
        int ti = t + k - (D_CONV - 1);
        if (ti >= 0) acc += xz[ti * (2 * D_INNER) + d] * conv_w[d * D_CONV + k];
    }
    float e = __expf(-acc);
    acc = acc * __frcp_rn(1.f + e);  // silu
    xc[t * D_INNER + d] = acc;
}

// ---------------- transpose [t][d] -> [d][t] for dt and xc ----------------
__global__ void transpose2_kernel(const float* __restrict__ in0, float* __restrict__ out0,
                                  const float* __restrict__ in1, float* __restrict__ out1)
{
    __shared__ float tile[32][33];
    const float* in  = blockIdx.z ? in1  : in0;
    float*       out = blockIdx.z ? out1 : out0;
    int t0 = blockIdx.y * 32;
    int d0 = blockIdx.x * 32;
    int tx = threadIdx.x, ty = threadIdx.y;
    #pragma unroll
    for (int i = 0; i < 32; i += 8)
        tile[ty + i][tx] = in[(t0 + ty + i) * D_INNER + d0 + tx];
    __syncthreads();
    #pragma unroll
    for (int i = 0; i < 32; i += 8)
        out[(d0 + ty + i) * L_SEQ + t0 + tx] = tile[tx][ty + i];
}

// ---------------- selective scan + skip + gating ----------------
__global__ void scan_kernel(const float* __restrict__ dbl,
                            const float* __restrict__ dtT,
                            const float* __restrict__ xcT,
                            const float* __restrict__ xz,
                            const float* __restrict__ A_log,
                            const float* __restrict__ D_skip,
                            float* __restrict__ y)
{
    __shared__ float bc[32][128];   // [step][ B(64) | C(64) ]
    int warp = threadIdx.x >> 5, lane = threadIdx.x & 31;
    int d = blockIdx.x * 8 + warp;

    float A0 = -__expf(A_log[d * D_STATE + lane]);
    float A1 = -__expf(A_log[d * D_STATE + lane + 32]);
    float Dd = D_skip[d];
    float h0 = 0.f, h1 = 0.f;

    for (int tc = 0; tc < L_SEQ; tc += 32) {
        float dt_r = dtT[d * L_SEQ + tc + lane];
        float xc_r = xcT[d * L_SEQ + tc + lane];
        __syncthreads();
        #pragma unroll
        for (int e = threadIdx.x; e < 32 * 128; e += 256) {
            int r = e >> 7, c = e & 127;
            bc[r][c] = dbl[(tc + r) * DBL_N + DT_RANK + c];
        }
        __syncthreads();
        #pragma unroll 4
        for (int j = 0; j < 32; j++) {
            float dt_t = __shfl_sync(0xffffffffu, dt_r, j);
            float x_t  = __shfl_sync(0xffffffffu, xc_r, j);
            float b0 = bc[j][lane],      b1 = bc[j][lane + 32];
            float c0 = bc[j][64 + lane], c1 = bc[j][96 + lane];
            float dx = dt_t * x_t;
            h0 = __expf(dt_t * A0) * h0 + dx * b0;
            h1 = __expf(dt_t * A1) * h1 + dx * b1;
            float ys = h0 * c0 + h1 * c1;
            ys += __shfl_xor_sync(0xffffffffu, ys, 16);
            ys += __shfl_xor_sync(0xffffffffu, ys, 8);
            ys += __shfl_xor_sync(0xffffffffu, ys, 4);
            ys += __shfl_xor_sync(0xffffffffu, ys, 2);
            ys += __shfl_xor_sync(0xffffffffu, ys, 1);
            if (lane == 0) {
                int t = tc + j;
                float zv = xz[t * (2 * D_INNER) + D_INNER + d];
                float sz = zv * __frcp_rn(1.f + __expf(-zv));     // silu(z)
                y[t * D_INNER + d] = (ys + x_t * Dd) * sz;
            }
        }
    }
}

// ---------------- host launcher ----------------
static constexpr int smem_bytes(int BM, int BN, int BK) {
    return (BM * (BK + 4) + BK * (BN + 4)) * 2 * 4;
}

extern "C" void kernel_launch(void* const* d_in, const int* in_sizes, int n_in,
                              void* d_out, int out_size)
{
    const float* x      = (const float*)d_in[0];
    const float* ln_g   = (const float*)d_in[1];
    const float* ln_b   = (const float*)d_in[2];
    const float* W_in   = (const float*)d_in[3];
    const float* conv_w = (const float*)d_in[4];
    const float* conv_b = (const float*)d_in[5];
    const float* W_x    = (const float*)d_in[6];
    const float* W_dt   = (const float*)d_in[7];
    const float* b_dt   = (const float*)d_in[8];
    const float* A_log  = (const float*)d_in[9];
    const float* D_skip = (const float*)d_in[10];
    const float* W_out  = (const float*)d_in[11];
    float* out = (float*)d_out;

    float *xn, *xz, *xc, *dbl, *dt, *xcT, *dtT, *y, *part;
    cudaGetSymbolAddress((void**)&xn,   g_xn);
    cudaGetSymbolAddress((void**)&xz,   g_xz);
    cudaGetSymbolAddress((void**)&xc,   g_xc);
    cudaGetSymbolAddress((void**)&dbl,  g_dbl);
    cudaGetSymbolAddress((void**)&dt,   g_dt);
    cudaGetSymbolAddress((void**)&xcT,  g_xcT);
    cudaGetSymbolAddress((void**)&dtT,  g_dtT);
    cudaGetSymbolAddress((void**)&y,    g_y);
    cudaGetSymbolAddress((void**)&part, g_part);

    constexpr int SM_BIG   = smem_bytes(128, 128, 32);  // 70656
    constexpr int SM_SMALL = smem_bytes(128, 64, 32);   // 54272

    static bool attr_done = false;
    if (!attr_done) {
        cudaFuncSetAttribute(gemm_tf32<128,128,32>, cudaFuncAttributeMaxDynamicSharedMemorySize, SM_BIG);
        cudaFuncSetAttribute(gemm_tf32<128,64,32>,  cudaFuncAttributeMaxDynamicSharedMemorySize, SM_SMALL);
        attr_done = true;
    }

    // 1. LayerNorm
    ln_kernel<<<L_SEQ, 256>>>(x, ln_g, ln_b, xn);

    // 2. in-projection: xz = xn @ W_in   (M=1024, N=3072, K=768) -> 192 CTAs
    gemm_tf32<128,128,32><<<dim3(2 * D_INNER / 128, L_SEQ / 128, 1), GEMM_THREADS, SM_BIG>>>(
        xn, D_MODEL, W_in, 2 * D_INNER, xz, 2 * D_INNER,
        L_SEQ, 2 * D_INNER, D_MODEL, D_MODEL, nullptr, 0);

    // 3. causal depthwise conv + SiLU
    conv_silu_kernel<<<(L_SEQ * D_INNER + 255) / 256, 256>>>(xz, conv_w, conv_b, xc);

    // 4. x-projection: dbl = xc @ W_x   (M=1024, N=176, K=1536) split-K=8 -> 192 CTAs
    gemm_tf32<128,64,32><<<dim3(3, L_SEQ / 128, 8), GEMM_THREADS, SM_SMALL>>>(
        xc, D_INNER, W_x, DBL_N, part, DBL_N,
        L_SEQ, DBL_N, D_INNER, D_INNER / 8, nullptr, 0);
    reduce_split<<<(L_SEQ * DBL_N / 4 + 255) / 256, 256>>>(
        part, dbl, L_SEQ * DBL_N / 4, 8, L_SEQ * DBL_N);

    // 5. dt = softplus(dt_raw @ W_dt + b_dt)   (M=1024, N=1536, K=48) -> 192 CTAs
    gemm_tf32<128,64,32><<<dim3(D_INNER / 64, L_SEQ / 128, 1), GEMM_THREADS, SM_SMALL>>>(
        dbl, DBL_N, W_dt, D_INNER, dt, D_INNER,
        L_SEQ, D_INNER, DT_RANK, DT_RANK, b_dt, 1);

    // 6. transpose dt, xc to [d][t]
    transpose2_kernel<<<dim3(D_INNER / 32, L_SEQ / 32, 2), dim3(32, 8)>>>(dt, dtT, xc, xcT);

    // 7. selective scan + D-skip + z gating
    scan_kernel<<<D_INNER / 8, 256>>>(dbl, dtT, xcT, xz, A_log, D_skip, y);

    // 8. out-projection: out = y @ W_out   (M=1024, N=768, K=1536) split-K=4 -> 384 CTAs
    gemm_tf32<128,64,32><<<dim3(D_MODEL / 64, L_SEQ / 128, 4), GEMM_THREADS, SM_SMALL>>>(
        y, D_INNER, W_out, D_MODEL, part, D_MODEL,
        L_SEQ, D_MODEL, D_INNER, D_INNER / 4, nullptr, 0);
    reduce_split<<<(L_SEQ * D_MODEL / 4 + 255) / 256, 256>>>(
        part, out, L_SEQ * D_MODEL / 4, 4, L_SEQ * D_MODEL);
}

// round 5
// speedup vs baseline: 2.1913x; 1.2424x over previous
#include <cstdint>
#include <cuda_runtime.h>
#include <cuda_bf16.h>
#include <mma.h>

using namespace nvcuda;

// ---------------- problem constants ----------------
#define L_SEQ   1024
#define D_MODEL 768
#define D_INNER 1536
#define D_STATE 64
#define D_CONV  4
#define DT_RANK 48
#define DBL_N   (DT_RANK + 2*D_STATE)   // 176
#define LN_EPS  1e-5f

#define GEMM_THREADS 256

// ---------------- scratch (no allocations allowed) ----------------
__device__ float g_xn [L_SEQ * D_MODEL];
__device__ float g_xz [L_SEQ * 2 * D_INNER];
__device__ float g_xc [L_SEQ * D_INNER];
__device__ float g_dbl[L_SEQ * DBL_N];
__device__ float g_dt [L_SEQ * D_INNER];
__device__ float g_xcT[D_INNER * L_SEQ];
__device__ float g_dtT[D_INNER * L_SEQ];
__device__ float g_zsT[D_INNER * L_SEQ];
__device__ float g_y  [L_SEQ * D_INNER];
__device__ float g_part[4 * L_SEQ * D_MODEL];   // split-K partials

// ---------------- cp.async helpers ----------------
__device__ __forceinline__ void cp_async16(void* smem_dst, const void* gmem_src) {
    unsigned int dst = (unsigned int)__cvta_generic_to_shared(smem_dst);
    asm volatile("cp.async.cg.shared.global [%0], [%1], 16;\n" :: "r"(dst), "l"(gmem_src));
}
__device__ __forceinline__ void cp_async_commit() {
    asm volatile("cp.async.commit_group;\n");
}
template<int N>
__device__ __forceinline__ void cp_async_wait() {
    asm volatile("cp.async.wait_group %0;\n" :: "n"(N));
}

// ---------------- LayerNorm ----------------
__global__ void ln_kernel(const float* __restrict__ x, const float* __restrict__ g,
                          const float* __restrict__ b, float* __restrict__ xn)
{
    int t = blockIdx.x;
    const float* xr = x + t * D_MODEL;
    float s = 0.f, s2 = 0.f;
    for (int i = threadIdx.x; i < D_MODEL; i += 256) {
        float v = xr[i];
        s += v; s2 += v * v;
    }
    #pragma unroll
    for (int o = 16; o; o >>= 1) {
        s  += __shfl_xor_sync(0xffffffffu, s,  o);
        s2 += __shfl_xor_sync(0xffffffffu, s2, o);
    }
    __shared__ float ss[8], ss2[8];
    __shared__ float mu_s, rstd_s;
    if ((threadIdx.x & 31) == 0) { ss[threadIdx.x >> 5] = s; ss2[threadIdx.x >> 5] = s2; }
    __syncthreads();
    if (threadIdx.x == 0) {
        float a = 0.f, a2 = 0.f;
        #pragma unroll
        for (int i = 0; i < 8; i++) { a += ss[i]; a2 += ss2[i]; }
        float mu = a / (float)D_MODEL;
        float var = a2 / (float)D_MODEL - mu * mu;
        mu_s = mu;
        rstd_s = rsqrtf(var + LN_EPS);
    }
    __syncthreads();
    float mu = mu_s, rstd = rstd_s;
    for (int i = threadIdx.x; i < D_MODEL; i += 256)
        xn[t * D_MODEL + i] = (xr[i] - mu) * rstd * g[i] + b[i];
}

// ---------------- templated tf32 WMMA GEMM, cp.async double-buffered, split-K ----------------
template<int BM, int BN, int BK>
__global__ void __launch_bounds__(GEMM_THREADS)
gemm_tf32(const float* __restrict__ A, int lda,
          const float* __restrict__ B, int ldb,
          float* __restrict__ C, int ldc,
          int M, int N, int K, int Kslice,
          const float* __restrict__ bias, int epilogue)
{
    constexpr int ALD = BK + 4;
    constexpr int BLD = BN + 4;
    constexpr int CLD = BN + 4;
    constexpr int FM = BM / 4 / 16;
    constexpr int FN = BN / 2 / 16;

    extern __shared__ float smem[];
    float* As[2] = { smem, smem + BM*ALD + BK*BLD };
    float* Bs[2] = { smem + BM*ALD, smem + 2*BM*ALD + BK*BLD };

    const int tid  = threadIdx.x;
    const int warp = tid >> 5;
    const int wr   = warp >> 1;
    const int wc   = warp & 1;
    const int row_base = blockIdx.y * BM;
    const int col_base = blockIdx.x * BN;

    const int k_begin = blockIdx.z * Kslice;
    const int k_end   = min(K, k_begin + Kslice);
    if (gridDim.z > 1) C += (size_t)blockIdx.z * M * ldc;

    const float4 zero4 = make_float4(0.f, 0.f, 0.f, 0.f);

    auto load_stage = [&](int s, int k0) {
        #pragma unroll
        for (int i = 0; i < BM*BK/4/GEMM_THREADS; i++) {
            int idx = tid + i * GEMM_THREADS;
            int r = idx / (BK/4), ch = idx % (BK/4);
            int gc = k0 + ch * 4;
            float* dst = &As[s][r * ALD + ch * 4];
            if (gc + 4 <= k_end) cp_async16(dst, &A[(row_base + r) * (size_t)lda + gc]);
            else                 *(float4*)dst = zero4;
        }
        #pragma unroll
        for (int i = 0; i < BK*BN/4/GEMM_THREADS; i++) {
            int idx = tid + i * GEMM_THREADS;
            int r = idx / (BN/4), ch = idx % (BN/4);
            int gr = k0 + r, gc = col_base + ch * 4;
            float* dst = &Bs[s][r * BLD + ch * 4];
            if (gr < k_end && gc + 4 <= N) cp_async16(dst, &B[gr * (size_t)ldb + gc]);
            else                           *(float4*)dst = zero4;
        }
        cp_async_commit();
    };

    wmma::fragment<wmma::accumulator, 16, 16, 8, float> acc[FM][FN];
    #pragma unroll
    for (int i = 0; i < FM; i++)
        #pragma unroll
        for (int j = 0; j < FN; j++)
            wmma::fill_fragment(acc[i][j], 0.f);

    const int ntiles = (k_end - k_begin + BK - 1) / BK;
    load_stage(0, k_begin);

    for (int kt = 0; kt < ntiles; kt++) {
        int s = kt & 1;
        if (kt + 1 < ntiles) {
            load_stage(s ^ 1, k_begin + (kt + 1) * BK);
            cp_async_wait<1>();
        } else {
            cp_async_wait<0>();
        }
        __syncthreads();

        const float* Ac = As[s];
        const float* Bc = Bs[s];
        #pragma unroll
        for (int kk = 0; kk < BK; kk += 8) {
            wmma::fragment<wmma::matrix_a, 16, 16, 8, wmma::precision::tf32, wmma::row_major> af[FM];
            wmma::fragment<wmma::matrix_b, 16, 16, 8, wmma::precision::tf32, wmma::row_major> bf[FN];
            #pragma unroll
            for (int i = 0; i < FM; i++) {
                wmma::load_matrix_sync(af[i], &Ac[(wr * (BM/4) + i * 16) * ALD + kk], ALD);
                #pragma unroll
                for (int e = 0; e < af[i].num_elements; e++)
                    af[i].x[e] = wmma::__float_to_tf32(af[i].x[e]);
            }
            #pragma unroll
            for (int j = 0; j < FN; j++) {
                wmma::load_matrix_sync(bf[j], &Bc[kk * BLD + wc * (BN/2) + j * 16], BLD);
                #pragma unroll
                for (int e = 0; e < bf[j].num_elements; e++)
                    bf[j].x[e] = wmma::__float_to_tf32(bf[j].x[e]);
            }
            #pragma unroll
            for (int i = 0; i < FM; i++)
                #pragma unroll
                for (int j = 0; j < FN; j++)
                    wmma::mma_sync(acc[i][j], af[i], bf[j], acc[i][j]);
        }
        __syncthreads();
    }

    float* Cs = smem;
    #pragma unroll
    for (int i = 0; i < FM; i++)
        #pragma unroll
        for (int j = 0; j < FN; j++)
            wmma::store_matrix_sync(&Cs[(wr * (BM/4) + i * 16) * CLD + wc * (BN/2) + j * 16],
                                    acc[i][j], CLD, wmma::mem_row_major);
    __syncthreads();

    #pragma unroll
    for (int e = tid; e < BM * BN; e += GEMM_THREADS) {
        int r = e / BN, c = e % BN;
        int gr = row_base + r, gc = col_base + c;
        if (gr < M && gc < N) {
            float v = Cs[r * CLD + c];
            if (epilogue == 1) {
                v += bias[gc];
                v = fmaxf(v, 0.f) + log1pf(__expf(-fabsf(v)));   // stable softplus
            }
            C[gr * (size_t)ldc + gc] = v;
        }
    }
}

// ---------------- split-K reduce ----------------
__global__ void reduce_split(const float* __restrict__ part, float* __restrict__ out,
                             int n4, int nsplit, int stride)
{
    int i = blockIdx.x * 256 + threadIdx.x;
    if (i >= n4) return;
    const float4* p = (const float4*)part;
    int s4 = stride >> 2;
    float4 a = p[i];
    for (int z = 1; z < nsplit; z++) {
        float4 b = p[z * (size_t)s4 + i];
        a.x += b.x; a.y += b.y; a.z += b.z; a.w += b.w;
    }
    ((float4*)out)[i] = a;
}

// ---------------- depthwise causal conv (d_conv=4) + SiLU ----------------
__global__ void conv_silu_kernel(const float* __restrict__ xz,
                                 const float* __restrict__ conv_w,
                                 const float* __restrict__ conv_b,
                                 float* __restrict__ xc)
{
    int idx = blockIdx.x * 256 + threadIdx.x;
    if (idx >= L_SEQ * D_INNER) return;
    int t = idx / D_INNER, d = idx - t * D_INNER;
    float acc = conv_b[d];
    #pragma unroll
    for (int k = 0; k < D_CONV; k++) {
        int ti = t + k - (D_CONV - 1);
        if (ti >= 0) acc += xz[ti * (2 * D_INNER) + d] * conv_w[d * D_CONV + k];
    }
    float e = __expf(-acc);
    acc = acc * __frcp_rn(1.f + e);  // silu
    xc[t * D_INNER + d] = acc;
}

// ---------------- 3-way transpose [t][d] -> [d][t]: dt, xc, silu(z) ----------------
__global__ void transpose3_kernel(const float* __restrict__ dt,  float* __restrict__ dtT,
                                  const float* __restrict__ xc,  float* __restrict__ xcT,
                                  const float* __restrict__ xz,  float* __restrict__ zsT)
{
    __shared__ float tile[32][33];
    const float* in; float* out; int stride; bool act;
    if (blockIdx.z == 0)      { in = dt;            out = dtT; stride = D_INNER;     act = false; }
    else if (blockIdx.z == 1) { in = xc;            out = xcT; stride = D_INNER;     act = false; }
    else                      { in = xz + D_INNER;  out = zsT; stride = 2 * D_INNER; act = true;  }
    int t0 = blockIdx.y * 32;
    int d0 = blockIdx.x * 32;
    int tx = threadIdx.x, ty = threadIdx.y;
    #pragma unroll
    for (int i = 0; i < 32; i += 8)
        tile[ty + i][tx] = in[(t0 + ty + i) * (size_t)stride + d0 + tx];
    __syncthreads();
    #pragma unroll
    for (int i = 0; i < 32; i += 8) {
        float v = tile[tx][ty + i];
        if (act) v = v * __frcp_rn(1.f + __expf(-v));    // silu
        out[(d0 + ty + i) * (size_t)L_SEQ + t0 + tx] = v;
    }
}

// ---------------- selective scan + skip + gating (batched, stall-free inner loop) ----------------
// 1 warp = 1 channel d; lane l owns states l and l+32. 8 warps/CTA share B/C in smem.
__global__ void scan_kernel(const float* __restrict__ dbl,
                            const float* __restrict__ dtT,
                            const float* __restrict__ xcT,
                            const float* __restrict__ zsT,
                            const float* __restrict__ A_log,
                            const float* __restrict__ D_skip,
                            float* __restrict__ y)
{
    __shared__ float bc[32][128];   // [step][ B(64) | C(64) ]
    const int warp = threadIdx.x >> 5, lane = threadIdx.x & 31;
    const int d = blockIdx.x * 8 + warp;

    const float A0 = -__expf(A_log[d * D_STATE + lane]);
    const float A1 = -__expf(A_log[d * D_STATE + lane + 32]);
    const float Dd = D_skip[d];
    float h0 = 0.f, h1 = 0.f;

    for (int tc = 0; tc < L_SEQ; tc += 32) {
        float dt_r = dtT[d * L_SEQ + tc + lane];
        float xc_r = xcT[d * L_SEQ + tc + lane];
        float zs_r = zsT[d * L_SEQ + tc + lane];
        __syncthreads();
        #pragma unroll
        for (int e = threadIdx.x; e < 32 * 128; e += 256) {
            int r = e >> 7, c = e & 127;
            bc[r][c] = dbl[(tc + r) * DBL_N + DT_RANK + c];
        }
        __syncthreads();

        #pragma unroll
        for (int js = 0; js < 32; js += 8) {
            // ---- phase 1: everything independent of the h-chain (pipelines freely) ----
            float dA0[8], dA1[8], dxb0[8], dxb1[8], cc0[8], cc1[8];
            #pragma unroll
            for (int j = 0; j < 8; j++) {
                float dt_t = __shfl_sync(0xffffffffu, dt_r, js + j);
                float x_t  = __shfl_sync(0xffffffffu, xc_r, js + j);
                dA0[j] = __expf(dt_t * A0);
                dA1[j] = __expf(dt_t * A1);
                float dx = dt_t * x_t;
                dxb0[j] = dx * bc[js + j][lane];
                dxb1[j] = dx * bc[js + j][lane + 32];
                cc0[j]  = bc[js + j][64 + lane];
                cc1[j]  = bc[js + j][96 + lane];
            }
            // ---- phase 2: pure-FFMA recurrence (4-5 cyc/step chain) ----
            float ys[8];
            #pragma unroll
            for (int j = 0; j < 8; j++) {
                h0 = fmaf(dA0[j], h0, dxb0[j]);
                h1 = fmaf(dA1[j], h1, dxb1[j]);
                ys[j] = h0 * cc0[j] + h1 * cc1[j];
            }
            // ---- phase 3: 8 interleaved butterfly reductions (latencies overlap) ----
            #pragma unroll
            for (int o = 16; o; o >>= 1) {
                #pragma unroll
                for (int j = 0; j < 8; j++)
                    ys[j] += __shfl_xor_sync(0xffffffffu, ys[j], o);
            }
            // ---- phase 4: lanes 0..7 write steps js..js+7 ----
            float x_l  = __shfl_sync(0xffffffffu, xc_r, js + (lane & 7));
            float zs_l = __shfl_sync(0xffffffffu, zs_r, js + (lane & 7));
            float yv = ys[0];
            #pragma unroll
            for (int j = 1; j < 8; j++)
                yv = (lane == j) ? ys[j] : yv;
            if (lane < 8) {
                int t = tc + js + lane;
                y[t * D_INNER + d] = (yv + x_l * Dd) * zs_l;
            }
        }
    }
}

// ---------------- host launcher ----------------
static constexpr int smem_bytes(int BM, int BN, int BK) {
    return (BM * (BK + 4) + BK * (BN + 4)) * 2 * 4;
}

extern "C" void kernel_launch(void* const* d_in, const int* in_sizes, int n_in,
                              void* d_out, int out_size)
{
    const float* x      = (const float*)d_in[0];
    const float* ln_g   = (const float*)d_in[1];
    const float* ln_b   = (const float*)d_in[2];
    const float* W_in   = (const float*)d_in[3];
    const float* conv_w = (const float*)d_in[4];
    const float* conv_b = (const float*)d_in[5];
    const float* W_x    = (const float*)d_in[6];
    const float* W_dt   = (const float*)d_in[7];
    const float* b_dt   = (const float*)d_in[8];
    const float* A_log  = (const float*)d_in[9];
    const float* D_skip = (const float*)d_in[10];
    const float* W_out  = (const float*)d_in[11];
    float* out = (float*)d_out;

    float *xn, *xz, *xc, *dbl, *dt, *xcT, *dtT, *zsT, *y, *part;
    cudaGetSymbolAddress((void**)&xn,   g_xn);
    cudaGetSymbolAddress((void**)&xz,   g_xz);
    cudaGetSymbolAddress((void**)&xc,   g_xc);
    cudaGetSymbolAddress((void**)&dbl,  g_dbl);
    cudaGetSymbolAddress((void**)&dt,   g_dt);
    cudaGetSymbolAddress((void**)&xcT,  g_xcT);
    cudaGetSymbolAddress((void**)&dtT,  g_dtT);
    cudaGetSymbolAddress((void**)&zsT,  g_zsT);
    cudaGetSymbolAddress((void**)&y,    g_y);
    cudaGetSymbolAddress((void**)&part, g_part);

    constexpr int SM_BIG   = smem_bytes(128, 128, 32);
    constexpr int SM_SMALL = smem_bytes(128, 64, 32);

    static bool attr_done = false;
    if (!attr_done) {
        cudaFuncSetAttribute(gemm_tf32<128,128,32>, cudaFuncAttributeMaxDynamicSharedMemorySize, SM_BIG);
        cudaFuncSetAttribute(gemm_tf32<128,64,32>,  cudaFuncAttributeMaxDynamicSharedMemorySize, SM_SMALL);
        attr_done = true;
    }

    // 1. LayerNorm
    ln_kernel<<<L_SEQ, 256>>>(x, ln_g, ln_b, xn);

    // 2. in-projection: xz = xn @ W_in   (M=1024, N=3072, K=768)
    gemm_tf32<128,128,32><<<dim3(2 * D_INNER / 128, L_SEQ / 128, 1), GEMM_THREADS, SM_BIG>>>(
        xn, D_MODEL, W_in, 2 * D_INNER, xz, 2 * D_INNER,
        L_SEQ, 2 * D_INNER, D_MODEL, D_MODEL, nullptr, 0);

    // 3. causal depthwise conv + SiLU
    conv_silu_kernel<<<(L_SEQ * D_INNER + 255) / 256, 256>>>(xz, conv_w, conv_b, xc);

    // 4. x-projection: dbl = xc @ W_x   (M=1024, N=176, K=1536) split-K=8
    gemm_tf32<128,64,32><<<dim3(3, L_SEQ / 128, 8), GEMM_THREADS, SM_SMALL>>>(
        xc, D_INNER, W_x, DBL_N, part, DBL_N,
        L_SEQ, DBL_N, D_INNER, D_INNER / 8, nullptr, 0);
    reduce_split<<<(L_SEQ * DBL_N / 4 + 255) / 256, 256>>>(
        part, dbl, L_SEQ * DBL_N / 4, 8, L_SEQ * DBL_N);

    // 5. dt = softplus(dt_raw @ W_dt + b_dt)   (M=1024, N=1536, K=48)
    gemm_tf32<128,64,32><<<dim3(D_INNER / 64, L_SEQ / 128, 1), GEMM_THREADS, SM_SMALL>>>(
        dbl, DBL_N, W_dt, D_INNER, dt, D_INNER,
        L_SEQ, D_INNER, DT_RANK, DT_RANK, b_dt, 1);

    // 6. transpose dt, xc, silu(z) to [d][t]
    transpose3_kernel<<<dim3(D_INNER / 32, L_SEQ / 32, 3), dim3(32, 8)>>>(
        dt, dtT, xc, xcT, xz, zsT);

    // 7. selective scan + D-skip + z gating
    scan_kernel<<<D_INNER / 8, 256>>>(dbl, dtT, xcT, zsT, A_log, D_skip, y);

    // 8. out-projection: out = y @ W_out   (M=1024, N=768, K=1536) split-K=4
    gemm_tf32<128,64,32><<<dim3(D_MODEL / 64, L_SEQ / 128, 4), GEMM_THREADS, SM_SMALL>>>(
        y, D_INNER, W_out, D_MODEL, part, D_MODEL,
        L_SEQ, D_MODEL, D_INNER, D_INNER / 4, nullptr, 0);
    reduce_split<<<(L_SEQ * D_MODEL / 4 + 255) / 256, 256>>>(
        part, out, L_SEQ * D_MODEL / 4, 4, L_SEQ * D_MODEL);
}

// round 6
// speedup vs baseline: 3.3440x; 1.5260x over previous
#include <cstdint>
#include <cuda_runtime.h>
#include <cuda_bf16.h>
#include <mma.h>

using namespace nvcuda;

// ---------------- problem constants ----------------
#define L_SEQ   1024
#define D_MODEL 768
#define D_INNER 1536
#define D_STATE 64
#define D_CONV  4
#define DT_RANK 48
#define DBL_N   (DT_RANK + 2*D_STATE)   // 176
#define LN_EPS  1e-5f

#define GEMM_THREADS 256

// ---------------- scratch (no allocations allowed) ----------------
__device__ float g_xn [L_SEQ * D_MODEL];
__device__ float g_xz [L_SEQ * 2 * D_INNER];
__device__ float g_xc [L_SEQ * D_INNER];
__device__ float g_dbl[L_SEQ * DBL_N];
__device__ float g_xcT[D_INNER * L_SEQ];
__device__ float g_dtT[D_INNER * L_SEQ];
__device__ float g_zsT[D_INNER * L_SEQ];
__device__ float g_y  [L_SEQ * D_INNER];
__device__ float g_part[8 * L_SEQ * DBL_N > 4 * L_SEQ * D_MODEL ?
                        8 * L_SEQ * DBL_N : 4 * L_SEQ * D_MODEL];
__device__ int   g_cnt[256];   // zero-initialized; each finisher resets its slot

// ---------------- cp.async helpers ----------------
__device__ __forceinline__ void cp_async16(void* smem_dst, const void* gmem_src) {
    unsigned int dst = (unsigned int)__cvta_generic_to_shared(smem_dst);
    asm volatile("cp.async.cg.shared.global [%0], [%1], 16;\n" :: "r"(dst), "l"(gmem_src));
}
__device__ __forceinline__ void cp_async_commit() {
    asm volatile("cp.async.commit_group;\n");
}
template<int N>
__device__ __forceinline__ void cp_async_wait() {
    asm volatile("cp.async.wait_group %0;\n" :: "n"(N));
}

// ---------------- LayerNorm ----------------
__global__ void ln_kernel(const float* __restrict__ x, const float* __restrict__ g,
                          const float* __restrict__ b, float* __restrict__ xn)
{
    int t = blockIdx.x;
    const float* xr = x + t * D_MODEL;
    float s = 0.f, s2 = 0.f;
    for (int i = threadIdx.x; i < D_MODEL; i += 256) {
        float v = xr[i];
        s += v; s2 += v * v;
    }
    #pragma unroll
    for (int o = 16; o; o >>= 1) {
        s  += __shfl_xor_sync(0xffffffffu, s,  o);
        s2 += __shfl_xor_sync(0xffffffffu, s2, o);
    }
    __shared__ float ss[8], ss2[8];
    __shared__ float mu_s, rstd_s;
    if ((threadIdx.x & 31) == 0) { ss[threadIdx.x >> 5] = s; ss2[threadIdx.x >> 5] = s2; }
    __syncthreads();
    if (threadIdx.x == 0) {
        float a = 0.f, a2 = 0.f;
        #pragma unroll
        for (int i = 0; i < 8; i++) { a += ss[i]; a2 += ss2[i]; }
        float mu = a / (float)D_MODEL;
        float var = a2 / (float)D_MODEL - mu * mu;
        mu_s = mu;
        rstd_s = rsqrtf(var + LN_EPS);
    }
    __syncthreads();
    float mu = mu_s, rstd = rstd_s;
    for (int i = threadIdx.x; i < D_MODEL; i += 256)
        xn[t * D_MODEL + i] = (xr[i] - mu) * rstd * g[i] + b[i];
}

// ---------------- tf32 WMMA GEMM: cp.async double-buffered, fused split-K reduce ----------------
// If gridDim.z > 1: each z-block writes its partial to part[z*M*ldc ...]; the last
// CTA per (x,y) tile sums partials in fixed z order (deterministic) and writes Cfinal.
// epilogue: 0 = plain; 1 = softplus(v + bias[col]) + TRANSPOSED store:
//           Cfinal[(col_base+dl)*ldc + row_base+tl]  (ldc = transposed leading dim).
template<int BM, int BN, int BK>
__global__ void __launch_bounds__(GEMM_THREADS)
gemm_tf32(const float* __restrict__ A, int lda,
          const float* __restrict__ B, int ldb,
          float* __restrict__ part, float* __restrict__ Cfinal, int ldc,
          int M, int N, int K, int Kslice,
          const float* __restrict__ bias, int epilogue)
{
    constexpr int ALD = BK + 4;
    constexpr int BLD = BN + 4;
    constexpr int CLD = BN + 4;
    constexpr int FM = BM / 4 / 16;
    constexpr int FN = BN / 2 / 16;

    extern __shared__ float smem[];
    float* As[2] = { smem, smem + BM*ALD + BK*BLD };
    float* Bs[2] = { smem + BM*ALD, smem + 2*BM*ALD + BK*BLD };

    const int tid  = threadIdx.x;
    const int warp = tid >> 5;
    const int wr   = warp >> 1;
    const int wc   = warp & 1;
    const int row_base = blockIdx.y * BM;
    const int col_base = blockIdx.x * BN;

    const int k_begin = blockIdx.z * Kslice;
    const int k_end   = min(K, k_begin + Kslice);

    const float4 zero4 = make_float4(0.f, 0.f, 0.f, 0.f);

    auto load_stage = [&](int s, int k0) {
        #pragma unroll
        for (int i = 0; i < BM*BK/4/GEMM_THREADS; i++) {
            int idx = tid + i * GEMM_THREADS;
            int r = idx / (BK/4), ch = idx % (BK/4);
            int gc = k0 + ch * 4;
            float* dst = &As[s][r * ALD + ch * 4];
            if (gc + 4 <= k_end) cp_async16(dst, &A[(row_base + r) * (size_t)lda + gc]);
            else                 *(float4*)dst = zero4;
        }
        #pragma unroll
        for (int i = 0; i < BK*BN/4/GEMM_THREADS; i++) {
            int idx = tid + i * GEMM_THREADS;
            int r = idx / (BN/4), ch = idx % (BN/4);
            int gr = k0 + r, gc = col_base + ch * 4;
            float* dst = &Bs[s][r * BLD + ch * 4];
            if (gr < k_end && gc + 4 <= N) cp_async16(dst, &B[gr * (size_t)ldb + gc]);
            else                           *(float4*)dst = zero4;
        }
        cp_async_commit();
    };

    wmma::fragment<wmma::accumulator, 16, 16, 8, float> acc[FM][FN];
    #pragma unroll
    for (int i = 0; i < FM; i++)
        #pragma unroll
        for (int j = 0; j < FN; j++)
            wmma::fill_fragment(acc[i][j], 0.f);

    const int ntiles = (k_end - k_begin + BK - 1) / BK;
    load_stage(0, k_begin);

    for (int kt = 0; kt < ntiles; kt++) {
        int s = kt & 1;
        if (kt + 1 < ntiles) {
            load_stage(s ^ 1, k_begin + (kt + 1) * BK);
            cp_async_wait<1>();
        } else {
            cp_async_wait<0>();
        }
        __syncthreads();

        const float* Ac = As[s];
        const float* Bc = Bs[s];
        #pragma unroll
        for (int kk = 0; kk < BK; kk += 8) {
            wmma::fragment<wmma::matrix_a, 16, 16, 8, wmma::precision::tf32, wmma::row_major> af[FM];
            wmma::fragment<wmma::matrix_b, 16, 16, 8, wmma::precision::tf32, wmma::row_major> bf[FN];
            #pragma unroll
            for (int i = 0; i < FM; i++) {
                wmma::load_matrix_sync(af[i], &Ac[(wr * (BM/4) + i * 16) * ALD + kk], ALD);
                #pragma unroll
                for (int e = 0; e < af[i].num_elements; e++)
                    af[i].x[e] = wmma::__float_to_tf32(af[i].x[e]);
            }
            #pragma unroll
            for (int j = 0; j < FN; j++) {
                wmma::load_matrix_sync(bf[j], &Bc[kk * BLD + wc * (BN/2) + j * 16], BLD);
                #pragma unroll
                for (int e = 0; e < bf[j].num_elements; e++)
                    bf[j].x[e] = wmma::__float_to_tf32(bf[j].x[e]);
            }
            #pragma unroll
            for (int i = 0; i < FM; i++)
                #pragma unroll
                for (int j = 0; j < FN; j++)
                    wmma::mma_sync(acc[i][j], af[i], bf[j], acc[i][j]);
        }
        __syncthreads();
    }

    float* Cs = smem;
    #pragma unroll
    for (int i = 0; i < FM; i++)
        #pragma unroll
        for (int j = 0; j < FN; j++)
            wmma::store_matrix_sync(&Cs[(wr * (BM/4) + i * 16) * CLD + wc * (BN/2) + j * 16],
                                    acc[i][j], CLD, wmma::mem_row_major);
    __syncthreads();

    if (gridDim.z == 1) {
        if (epilogue == 1) {
            // softplus + transposed store (dt path): ldc is the transposed leading dim
            #pragma unroll
            for (int e = tid; e < BM * BN; e += GEMM_THREADS) {
                int tl = e % BM, dl = e / BM;
                int gr = row_base + tl, gc = col_base + dl;
                if (gr < M && gc < N) {
                    float v = Cs[tl * CLD + dl] + bias[gc];
                    v = fmaxf(v, 0.f) + log1pf(__expf(-fabsf(v)));
                    Cfinal[gc * (size_t)ldc + gr] = v;
                }
            }
        } else {
            #pragma unroll
            for (int e = tid; e < BM * BN; e += GEMM_THREADS) {
                int r = e / BN, c = e % BN;
                int gr = row_base + r, gc = col_base + c;
                if (gr < M && gc < N)
                    Cfinal[gr * (size_t)ldc + gc] = Cs[r * CLD + c];
            }
        }
        return;
    }

    // ---- fused split-K: write partial, last CTA reduces deterministically ----
    float* myp = part + (size_t)blockIdx.z * M * ldc;
    #pragma unroll
    for (int e = tid; e < BM * BN; e += GEMM_THREADS) {
        int r = e / BN, c = e % BN;
        int gr = row_base + r, gc = col_base + c;
        if (gr < M && gc < N)
            myp[gr * (size_t)ldc + gc] = Cs[r * CLD + c];
    }
    __threadfence();
    __syncthreads();

    __shared__ int is_last;
    const int tile = blockIdx.y * gridDim.x + blockIdx.x;
    if (tid == 0)
        is_last = (atomicAdd(&g_cnt[tile], 1) == (int)gridDim.z - 1);
    __syncthreads();
    if (!is_last) return;
    __threadfence();

    const int nz = gridDim.z;
    for (int e = tid; e < BM * BN; e += GEMM_THREADS) {
        int r = e / BN, c = e % BN;
        int gr = row_base + r, gc = col_base + c;
        if (gr < M && gc < N) {
            size_t off = gr * (size_t)ldc + gc;
            float v = 0.f;
            for (int z = 0; z < nz; z++)      // fixed order -> deterministic
                v += part[(size_t)z * M * ldc + off];
            Cfinal[off] = v;
        }
    }
    if (tid == 0) g_cnt[tile] = 0;            // reset for next graph replay
}

// ---------------- conv(d_conv=4)+SiLU -> xc, xcT  and  silu(z) -> zsT ----------------
// grid (D_INNER/32, L_SEQ/128), block (32,8). Tile: 32 channels x 128 timesteps.
__global__ void conv_fused_kernel(const float* __restrict__ xz,
                                  const float* __restrict__ conv_w,
                                  const float* __restrict__ conv_b,
                                  float* __restrict__ xc,
                                  float* __restrict__ xcT,
                                  float* __restrict__ zsT)
{
    __shared__ float xs[131][33];
    __shared__ float buf[128][33];
    const int tx = threadIdx.x, ty = threadIdx.y;
    const int d0 = blockIdx.x * 32;
    const int t0 = blockIdx.y * 128;
    const int d  = d0 + tx;

    // load x-half rows t0-3 .. t0+127
    for (int i = ty; i < 131; i += 8) {
        int t = t0 - 3 + i;
        xs[i][tx] = (t >= 0) ? xz[t * (2 * D_INNER) + d] : 0.f;
    }
    const float w0 = conv_w[d * D_CONV + 0];
    const float w1 = conv_w[d * D_CONV + 1];
    const float w2 = conv_w[d * D_CONV + 2];
    const float w3 = conv_w[d * D_CONV + 3];
    const float cb = conv_b[d];
    __syncthreads();

    for (int i = ty; i < 128; i += 8) {
        float acc = cb + xs[i][tx] * w0 + xs[i+1][tx] * w1 + xs[i+2][tx] * w2 + xs[i+3][tx] * w3;
        acc = acc * __frcp_rn(1.f + __expf(-acc));   // silu
        xc[(t0 + i) * D_INNER + d] = acc;
        buf[i][tx] = acc;
    }
    __syncthreads();
    // transposed write: xcT[d][t]
    #pragma unroll
    for (int jj = 0; jj < 4; jj++) {
        int t = tx + jj * 32;
        for (int i = ty; i < 32; i += 8)
            xcT[(d0 + i) * (size_t)L_SEQ + t0 + t] = buf[t][i];
    }
    __syncthreads();
    // z-half: silu -> zsT
    for (int i = ty; i < 128; i += 8) {
        float v = xz[(t0 + i) * (2 * D_INNER) + D_INNER + d];
        buf[i][tx] = v * __frcp_rn(1.f + __expf(-v));
    }
    __syncthreads();
    #pragma unroll
    for (int jj = 0; jj < 4; jj++) {
        int t = tx + jj * 32;
        for (int i = ty; i < 32; i += 8)
            zsT[(d0 + i) * (size_t)L_SEQ + t0 + t] = buf[t][i];
    }
}

// ---------------- selective scan + skip + gating (batched) ----------------
__global__ void scan_kernel(const float* __restrict__ dbl,
                            const float* __restrict__ dtT,
                            const float* __restrict__ xcT,
                            const float* __restrict__ zsT,
                            const float* __restrict__ A_log,
                            const float* __restrict__ D_skip,
                            float* __restrict__ y)
{
    __shared__ float bc[32][128];
    const int warp = threadIdx.x >> 5, lane = threadIdx.x & 31;
    const int d = blockIdx.x * 8 + warp;

    const float A0 = -__expf(A_log[d * D_STATE + lane]);
    const float A1 = -__expf(A_log[d * D_STATE + lane + 32]);
    const float Dd = D_skip[d];
    float h0 = 0.f, h1 = 0.f;

    for (int tc = 0; tc < L_SEQ; tc += 32) {
        float dt_r = dtT[d * L_SEQ + tc + lane];
        float xc_r = xcT[d * L_SEQ + tc + lane];
        float zs_r = zsT[d * L_SEQ + tc + lane];
        __syncthreads();
        #pragma unroll
        for (int e = threadIdx.x; e < 32 * 128; e += 256) {
            int r = e >> 7, c = e & 127;
            bc[r][c] = dbl[(tc + r) * DBL_N + DT_RANK + c];
        }
        __syncthreads();

        #pragma unroll
        for (int js = 0; js < 32; js += 8) {
            float dA0[8], dA1[8], dxb0[8], dxb1[8], cc0[8], cc1[8];
            #pragma unroll
            for (int j = 0; j < 8; j++) {
                float dt_t = __shfl_sync(0xffffffffu, dt_r, js + j);
                float x_t  = __shfl_sync(0xffffffffu, xc_r, js + j);
                dA0[j] = __expf(dt_t * A0);
                dA1[j] = __expf(dt_t * A1);
                float dx = dt_t * x_t;
                dxb0[j] = dx * bc[js + j][lane];
                dxb1[j] = dx * bc[js + j][lane + 32];
                cc0[j]  = bc[js + j][64 + lane];
                cc1[j]  = bc[js + j][96 + lane];
            }
            float ys[8];
            #pragma unroll
            for (int j = 0; j < 8; j++) {
                h0 = fmaf(dA0[j], h0, dxb0[j]);
                h1 = fmaf(dA1[j], h1, dxb1[j]);
                ys[j] = h0 * cc0[j] + h1 * cc1[j];
            }
            #pragma unroll
            for (int o = 16; o; o >>= 1) {
                #pragma unroll
                for (int j = 0; j < 8; j++)
                    ys[j] += __shfl_xor_sync(0xffffffffu, ys[j], o);
            }
            float x_l  = __shfl_sync(0xffffffffu, xc_r, js + (lane & 7));
            float zs_l = __shfl_sync(0xffffffffu, zs_r, js + (lane & 7));
            float yv = ys[0];
            #pragma unroll
            for (int j = 1; j < 8; j++)
                yv = (lane == j) ? ys[j] : yv;
            if (lane < 8) {
                int t = tc + js + lane;
                y[t * D_INNER + d] = (yv + x_l * Dd) * zs_l;
            }
        }
    }
}

// ---------------- host launcher ----------------
static constexpr int smem_bytes(int BM, int BN, int BK) {
    return (BM * (BK + 4) + BK * (BN + 4)) * 2 * 4;
}

extern "C" void kernel_launch(void* const* d_in, const int* in_sizes, int n_in,
                              void* d_out, int out_size)
{
    const float* x      = (const float*)d_in[0];
    const float* ln_g   = (const float*)d_in[1];
    const float* ln_b   = (const float*)d_in[2];
    const float* W_in   = (const float*)d_in[3];
    const float* conv_w = (const float*)d_in[4];
    const float* conv_b = (const float*)d_in[5];
    const float* W_x    = (const float*)d_in[6];
    const float* W_dt   = (const float*)d_in[7];
    const float* b_dt   = (const float*)d_in[8];
    const float* A_log  = (const float*)d_in[9];
    const float* D_skip = (const float*)d_in[10];
    const float* W_out  = (const float*)d_in[11];
    float* out = (float*)d_out;

    float *xn, *xz, *xc, *dbl, *xcT, *dtT, *zsT, *y, *part;
    cudaGetSymbolAddress((void**)&xn,   g_xn);
    cudaGetSymbolAddress((void**)&xz,   g_xz);
    cudaGetSymbolAddress((void**)&xc,   g_xc);
    cudaGetSymbolAddress((void**)&dbl,  g_dbl);
    cudaGetSymbolAddress((void**)&xcT,  g_xcT);
    cudaGetSymbolAddress((void**)&dtT,  g_dtT);
    cudaGetSymbolAddress((void**)&zsT,  g_zsT);
    cudaGetSymbolAddress((void**)&y,    g_y);
    cudaGetSymbolAddress((void**)&part, g_part);

    constexpr int SM_IN  = smem_bytes(64, 128, 32);  // 52224
    constexpr int SM_SM  = smem_bytes(64, 64, 32);   // 35840

    static bool attr_done = false;
    if (!attr_done) {
        cudaFuncSetAttribute(gemm_tf32<64,128,32>, cudaFuncAttributeMaxDynamicSharedMemorySize, SM_IN);
        cudaFuncSetAttribute(gemm_tf32<64,64,32>,  cudaFuncAttributeMaxDynamicSharedMemorySize, SM_SM);
        attr_done = true;
    }

    // 1. LayerNorm
    ln_kernel<<<L_SEQ, 256>>>(x, ln_g, ln_b, xn);

    // 2. in-projection: xz = xn @ W_in   (M=1024, N=3072, K=768) -> 384 CTAs
    gemm_tf32<64,128,32><<<dim3(2 * D_INNER / 128, L_SEQ / 64, 1), GEMM_THREADS, SM_IN>>>(
        xn, D_MODEL, W_in, 2 * D_INNER, nullptr, xz, 2 * D_INNER,
        L_SEQ, 2 * D_INNER, D_MODEL, D_MODEL, nullptr, 0);

    // 3. conv+SiLU -> xc, xcT;  silu(z) -> zsT
    conv_fused_kernel<<<dim3(D_INNER / 32, L_SEQ / 128), dim3(32, 8)>>>(
        xz, conv_w, conv_b, xc, xcT, zsT);

    // 4. x-projection: dbl = xc @ W_x  (M=1024, N=176, K=1536) split-K=8, fused reduce -> 384 CTAs
    gemm_tf32<64,64,32><<<dim3(3, L_SEQ / 64, 8), GEMM_THREADS, SM_SM>>>(
        xc, D_INNER, W_x, DBL_N, part, dbl, DBL_N,
        L_SEQ, DBL_N, D_INNER, D_INNER / 8, nullptr, 0);

    // 5. dtT = softplus(dt_raw @ W_dt + b_dt)^T  (M=1024, N=1536, K=48) -> 384 CTAs
    gemm_tf32<64,64,32><<<dim3(D_INNER / 64, L_SEQ / 64, 1), GEMM_THREADS, SM_SM>>>(
        dbl, DBL_N, W_dt, D_INNER, nullptr, dtT, L_SEQ,
        L_SEQ, D_INNER, DT_RANK, DT_RANK, b_dt, 1);

    // 6. selective scan + D-skip + z gating   (<- ncu -s 5 -c 1 lands here)
    scan_kernel<<<D_INNER / 8, 256>>>(dbl, dtT, xcT, zsT, A_log, D_skip, y);

    // 7. out-projection: out = y @ W_out  (M=1024, N=768, K=1536) split-K=4, fused reduce -> 768 CTAs
    gemm_tf32<64,64,32><<<dim3(D_MODEL / 64, L_SEQ / 64, 4), GEMM_THREADS, SM_SM>>>(
        y, D_INNER, W_out, D_MODEL, part, out, D_MODEL,
        L_SEQ, D_MODEL, D_INNER, D_INNER / 4, nullptr, 0);
}